// round 3
// baseline (speedup 1.0000x reference)
#include <cuda_runtime.h>
#include <math.h>

#define D     384
#define NH    8
#define HD    48
#define KN    10
#define NB    64
#define S     14
#define NDN   8192
#define NSEQ  640           // NB*KN
#define NTOK  8960          // NSEQ*S

// ---------------- scratch (device globals: allocation-free) ----------------
__device__ float g_sim[NB * S * NDN];        // (b, h, n)
__device__ int   g_idx[NB * S * KN];
__device__ float g_x   [NTOK * D];
__device__ float g_mem [NTOK * D];
__device__ float g_mem2[NTOK * D];
__device__ float g_h   [NTOK * D];
__device__ float g_qkv [NTOK * 3 * D];
__device__ float g_ao  [NTOK * D];
__device__ float g_ff  [NTOK * 4 * D];

// ---------------- sim = einsum('bhd,bnd->bhn') ----------------
__global__ __launch_bounds__(128) void sim_kernel(const float* __restrict__ qt,
                                                  const float* __restrict__ nd) {
    __shared__ float qs[S * D];
    int b = blockIdx.y;
    int tid = threadIdx.x;
    const float4* qb = (const float4*)(qt + (size_t)b * S * D);
    for (int i = tid; i < S * D / 4; i += 128) ((float4*)qs)[i] = qb[i];
    __syncthreads();

    int r0 = blockIdx.x * 256 + tid;
    int r1 = r0 + 128;
    const float4* n0 = (const float4*)(nd + ((size_t)b * NDN + r0) * D);
    const float4* n1 = (const float4*)(nd + ((size_t)b * NDN + r1) * D);
    const float4* q4 = (const float4*)qs;

    float acc0[S], acc1[S];
#pragma unroll
    for (int h = 0; h < S; h++) { acc0[h] = 0.f; acc1[h] = 0.f; }

    for (int d = 0; d < D / 4; d++) {
        float4 a = n0[d];
        float4 c = n1[d];
#pragma unroll
        for (int h = 0; h < S; h++) {
            float4 q = q4[h * (D / 4) + d];   // broadcast across warp
            acc0[h] += a.x * q.x + a.y * q.y + a.z * q.z + a.w * q.w;
            acc1[h] += c.x * q.x + c.y * q.y + c.z * q.z + c.w * q.w;
        }
    }
#pragma unroll
    for (int h = 0; h < S; h++) {
        g_sim[((size_t)b * S + h) * NDN + r0] = acc0[h];
        g_sim[((size_t)b * S + h) * NDN + r1] = acc1[h];
    }
}

// ---------------- top-k (k=10, sorted desc, tie -> lowest index) ----------------
__global__ __launch_bounds__(256) void topk_kernel() {
    int row = blockIdx.x;                 // 0..895 = b*14+h
    __shared__ float vals[NDN];
    __shared__ float sv[256];
    __shared__ int   si[256];
    int tid = threadIdx.x;
    const float4* src = (const float4*)(g_sim + (size_t)row * NDN);
    for (int i = tid; i < NDN / 4; i += 256) ((float4*)vals)[i] = src[i];
    __syncthreads();

    for (int k = 0; k < KN; k++) {
        float bv = -3.4e38f; int bi = 0;
        for (int j = tid; j < NDN; j += 256) {
            float v = vals[j];
            if (v > bv) { bv = v; bi = j; }     // ascending j => lowest idx on tie
        }
        sv[tid] = bv; si[tid] = bi;
        __syncthreads();
        for (int s = 128; s > 0; s >>= 1) {
            if (tid < s) {
                float v2 = sv[tid + s]; int i2 = si[tid + s];
                if (v2 > sv[tid] || (v2 == sv[tid] && i2 < si[tid])) { sv[tid] = v2; si[tid] = i2; }
            }
            __syncthreads();
        }
        if (tid == 0) { g_idx[row * KN + k] = si[0]; vals[si[0]] = -3.4e38f; }
        __syncthreads();
    }
}

// ---------------- build x (broadcast qt) and mem (gather) ----------------
__global__ __launch_bounds__(96) void init_kernel(const float* __restrict__ qt,
                                                  const float* __restrict__ nd) {
    int tok = blockIdx.x;        // 0..13
    int seq = blockIdx.y;        // 0..639
    int b = seq / KN, kn = seq - b * KN;
    int tid = threadIdx.x;       // 96 = 384/4
    const float4* qrow = (const float4*)(qt + ((size_t)b * S + tok) * D);
    int nid = g_idx[(b * S + tok) * KN + kn];
    const float4* nrow = (const float4*)(nd + ((size_t)b * NDN + nid) * D);
    float4* xr = (float4*)(g_x   + ((size_t)seq * S + tok) * D);
    float4* mr = (float4*)(g_mem + ((size_t)seq * S + tok) * D);
    xr[tid] = qrow[tid];
    mr[tid] = nrow[tid];
}

// ---------------- layernorm (one block per token) ----------------
__global__ __launch_bounds__(128) void ln_kernel(const float* __restrict__ src,
                                                 const float* __restrict__ w,
                                                 const float* __restrict__ b,
                                                 float* __restrict__ dst) {
    int row = blockIdx.x;
    int tid = threadIdx.x;
    const float* x = src + (size_t)row * D;
    float v0 = x[tid], v1 = x[tid + 128], v2 = x[tid + 256];
    float s  = v0 + v1 + v2;
    float s2 = v0 * v0 + v1 * v1 + v2 * v2;
    for (int o = 16; o > 0; o >>= 1) {
        s  += __shfl_xor_sync(0xffffffffu, s,  o);
        s2 += __shfl_xor_sync(0xffffffffu, s2, o);
    }
    __shared__ float ss[4], ss2[4];
    if ((tid & 31) == 0) { ss[tid >> 5] = s; ss2[tid >> 5] = s2; }
    __syncthreads();
    s  = ss[0]  + ss[1]  + ss[2]  + ss[3];
    s2 = ss2[0] + ss2[1] + ss2[2] + ss2[3];
    float mu  = s * (1.f / D);
    float var = s2 * (1.f / D) - mu * mu;
    float rs  = rsqrtf(var + 1e-5f);
    float* o = dst + (size_t)row * D;
    o[tid]       = (v0 - mu) * rs * w[tid]       + b[tid];
    o[tid + 128] = (v1 - mu) * rs * w[tid + 128] + b[tid + 128];
    o[tid + 256] = (v2 - mu) * rs * w[tid + 256] + b[tid + 256];
}

// ---------------- GEMM: C[M,N] = A[M,K] @ W[N,K]^T + bias (+epilogue) ----------------
// BM=128, BN=128, BK=16, 256 threads, 8x8 register tile.
// EPI: 0 = none, 1 = exact gelu, 2 = add residual (res has ld = D, N must be <= D)
template <int EPI>
__global__ __launch_bounds__(256) void gemm_kernel(const float* __restrict__ A, int lda,
                                                   const float* __restrict__ W, int ldw,
                                                   const float* __restrict__ bias,
                                                   float* __restrict__ C, int ldc,
                                                   const float* __restrict__ res,
                                                   int K) {
    __shared__ float As[16][132];
    __shared__ float Ws[16][132];
    int tid = threadIdx.x;
    int m0 = blockIdx.x * 128;
    int n0 = blockIdx.y * 128;
    int ty = tid >> 4, tx = tid & 15;
    int ms = ty * 8, ns = tx * 8;

    float acc[8][8];
#pragma unroll
    for (int i = 0; i < 8; i++)
#pragma unroll
        for (int j = 0; j < 8; j++) acc[i][j] = 0.f;

    for (int kt = 0; kt < K; kt += 16) {
#pragma unroll
        for (int l = 0; l < 2; l++) {
            int idx = tid + l * 256;
            int row = idx >> 2, kc = idx & 3;
            float4 v = *(const float4*)(A + (size_t)(m0 + row) * lda + kt + kc * 4);
            As[kc * 4 + 0][row] = v.x;
            As[kc * 4 + 1][row] = v.y;
            As[kc * 4 + 2][row] = v.z;
            As[kc * 4 + 3][row] = v.w;
        }
#pragma unroll
        for (int l = 0; l < 2; l++) {
            int idx = tid + l * 256;
            int n = idx >> 2, kc = idx & 3;
            float4 v = *(const float4*)(W + (size_t)(n0 + n) * ldw + kt + kc * 4);
            Ws[kc * 4 + 0][n] = v.x;
            Ws[kc * 4 + 1][n] = v.y;
            Ws[kc * 4 + 2][n] = v.z;
            Ws[kc * 4 + 3][n] = v.w;
        }
        __syncthreads();
#pragma unroll
        for (int k = 0; k < 16; k++) {
            float4 a0 = *(const float4*)&As[k][ms];
            float4 a1 = *(const float4*)&As[k][ms + 4];
            float4 w0 = *(const float4*)&Ws[k][ns];
            float4 w1 = *(const float4*)&Ws[k][ns + 4];
            float av[8] = {a0.x, a0.y, a0.z, a0.w, a1.x, a1.y, a1.z, a1.w};
            float wv[8] = {w0.x, w0.y, w0.z, w0.w, w1.x, w1.y, w1.z, w1.w};
#pragma unroll
            for (int i = 0; i < 8; i++)
#pragma unroll
                for (int j = 0; j < 8; j++) acc[i][j] += av[i] * wv[j];
        }
        __syncthreads();
    }

#pragma unroll
    for (int i = 0; i < 8; i++) {
        int m = m0 + ms + i;
#pragma unroll
        for (int j = 0; j < 8; j++) {
            int n = n0 + ns + j;
            float c = acc[i][j] + bias[n];
            if (EPI == 1) c = 0.5f * c * (1.f + erff(c * 0.70710678118654752f));
            if (EPI == 2) c += res[(size_t)m * D + n];
            C[(size_t)m * ldc + n] = c;
        }
    }
}

// ---------------- attention (one block per (head, seq)) ----------------
__global__ __launch_bounds__(256) void attn_kernel() {
    int head = blockIdx.x;     // 0..7
    int seq  = blockIdx.y;     // 0..639
    __shared__ float q[S * HD], k[S * HD], v[S * HD];
    __shared__ float sc[S][S + 2];
    int tid = threadIdx.x;
    size_t base = (size_t)seq * S * (3 * D) + head * HD;
    for (int idx = tid; idx < S * HD; idx += 256) {
        int i = idx / HD, e = idx - i * HD;
        size_t g = base + (size_t)i * (3 * D) + e;
        q[idx] = g_qkv[g];
        k[idx] = g_qkv[g + D];
        v[idx] = g_qkv[g + 2 * D];
    }
    __syncthreads();
    if (tid < S * S) {
        int i = tid / S, j = tid - i * S;
        float s = 0.f;
#pragma unroll
        for (int e = 0; e < HD; e++) s += q[i * HD + e] * k[j * HD + e];
        sc[i][j] = s * 0.14433756729740643f;   // 1/sqrt(48)
    }
    __syncthreads();
    if (tid < S) {
        float m = -3.4e38f;
        for (int j = 0; j < S; j++) m = fmaxf(m, sc[tid][j]);
        float e[S];
        float sum = 0.f;
        for (int j = 0; j < S; j++) { e[j] = expf(sc[tid][j] - m); sum += e[j]; }
        float inv = 1.f / sum;
        for (int j = 0; j < S; j++) sc[tid][j] = e[j] * inv;
    }
    __syncthreads();
    for (int idx = tid; idx < S * HD; idx += 256) {
        int i = idx / HD, e = idx - i * HD;
        float o = 0.f;
#pragma unroll
        for (int j = 0; j < S; j++) o += sc[i][j] * v[j * HD + e];
        g_ao[((size_t)seq * S + i) * D + head * HD + e] = o;
    }
}

// ---------------- copy mem2 -> x ----------------
__global__ __launch_bounds__(256) void copy_kernel(const float* __restrict__ src,
                                                   float* __restrict__ dst) {
    size_t i = (size_t)blockIdx.x * 256 + threadIdx.x;
    ((float4*)dst)[i] = ((const float4*)src)[i];
}

// ---------------- launch ----------------
extern "C" void kernel_launch(void* const* d_in, const int* in_sizes, int n_in,
                              void* d_out, int out_size) {
    const float* qt    = (const float*)d_in[0];
    const float* nd    = (const float*)d_in[1];
    const float* sa_w  = (const float*)d_in[2];
    const float* sa_b  = (const float*)d_in[3];
    const float* sa_ow = (const float*)d_in[4];
    const float* sa_ob = (const float*)d_in[5];
    const float* ca_w  = (const float*)d_in[6];
    const float* ca_b  = (const float*)d_in[7];
    const float* ca_ow = (const float*)d_in[8];
    const float* ca_ob = (const float*)d_in[9];
    const float* ln1w  = (const float*)d_in[10];
    const float* ln1b  = (const float*)d_in[11];
    const float* ln2w  = (const float*)d_in[12];
    const float* ln2b  = (const float*)d_in[13];
    const float* ln3w  = (const float*)d_in[14];
    const float* ln3b  = (const float*)d_in[15];
    const float* f1w   = (const float*)d_in[16];
    const float* f1b   = (const float*)d_in[17];
    const float* f2w   = (const float*)d_in[18];
    const float* f2b   = (const float*)d_in[19];
    const float* fnw   = (const float*)d_in[20];
    const float* fnb   = (const float*)d_in[21];
    float* out = (float*)d_out;

    // Resolve scratch addresses every call (no static caching — harness rule).
    float *p_x, *p_mem, *p_mem2, *p_h, *p_qkv, *p_ao, *p_ff;
    cudaGetSymbolAddress((void**)&p_x,    g_x);
    cudaGetSymbolAddress((void**)&p_mem,  g_mem);
    cudaGetSymbolAddress((void**)&p_mem2, g_mem2);
    cudaGetSymbolAddress((void**)&p_h,    g_h);
    cudaGetSymbolAddress((void**)&p_qkv,  g_qkv);
    cudaGetSymbolAddress((void**)&p_ao,   g_ao);
    cudaGetSymbolAddress((void**)&p_ff,   g_ff);

    sim_kernel<<<dim3(NDN / 256, NB), 128>>>(qt, nd);
    topk_kernel<<<NB * S, 256>>>();
    init_kernel<<<dim3(S, NSEQ), 96>>>(qt, nd);

    const int GM = NTOK / 128;   // 70
    for (int i = 0; i < 6; i++) {
        const float* memp = (i < 3) ? p_mem : p_mem2;
        // --- self attention ---
        ln_kernel<<<NTOK, 128>>>(p_x, ln1w + i * D, ln1b + i * D, p_h);
        gemm_kernel<0><<<dim3(GM, 9), 256>>>(p_h, D, sa_w + (size_t)i * 1152 * D, D,
                                             sa_b + i * 1152, p_qkv, 3 * D, nullptr, D);
        attn_kernel<<<dim3(NH, NSEQ), 256>>>();
        gemm_kernel<2><<<dim3(GM, 3), 256>>>(p_ao, D, sa_ow + (size_t)i * D * D, D,
                                             sa_ob + i * D, p_x, D, p_x, D);
        // --- cross attention ---
        ln_kernel<<<NTOK, 128>>>(p_x, ln2w + i * D, ln2b + i * D, p_h);
        gemm_kernel<0><<<dim3(GM, 3), 256>>>(p_h, D, ca_w + (size_t)i * 1152 * D, D,
                                             ca_b + i * 1152, p_qkv, 3 * D, nullptr, D);
        gemm_kernel<0><<<dim3(GM, 6), 256>>>(memp, D, ca_w + (size_t)i * 1152 * D + (size_t)D * D, D,
                                             ca_b + i * 1152 + D, p_qkv + D, 3 * D, nullptr, D);
        attn_kernel<<<dim3(NH, NSEQ), 256>>>();
        gemm_kernel<2><<<dim3(GM, 3), 256>>>(p_ao, D, ca_ow + (size_t)i * D * D, D,
                                             ca_ob + i * D, p_x, D, p_x, D);
        // --- FFN ---
        ln_kernel<<<NTOK, 128>>>(p_x, ln3w + i * D, ln3b + i * D, p_h);
        gemm_kernel<1><<<dim3(GM, 12), 256>>>(p_h, D, f1w + (size_t)i * 1536 * D, D,
                                              f1b + i * 1536, p_ff, 1536, nullptr, D);
        gemm_kernel<2><<<dim3(GM, 3), 256>>>(p_ff, 1536, f2w + (size_t)i * D * 1536, 1536,
                                             f2b + i * D, p_x, D, p_x, 1536);
        // --- mid final-norm: x = ln(x); mem2 = x ---
        if (i == 2) {
            ln_kernel<<<NTOK, 128>>>(p_x, fnw, fnb, p_mem2);
            copy_kernel<<<NTOK * D / 4 / 256, 256>>>(p_mem2, p_x);
        }
    }
    ln_kernel<<<NTOK, 128>>>(p_x, fnw + D, fnb + D, out);
}

// round 13
// speedup vs baseline: 1.9899x; 1.9899x over previous
#include <cuda_runtime.h>
#include <cuda_bf16.h>
#include <math.h>
#include <stdint.h>

#define D     384
#define NH    8
#define HD    48
#define KN    10
#define NB    64
#define S     14
#define NDN   8192
#define NSEQ  640           // NB*KN
#define NTOK  8960          // NSEQ*S

typedef __nv_bfloat16 bf16;

// ---------------- scratch (device globals: allocation-free) ----------------
__device__ float g_sim[NB * S * NDN];
__device__ int   g_idx[NB * S * KN];
__device__ float g_x   [NTOK * D];
__device__ float g_qkv [NTOK * 3 * D];

__device__ __align__(16) bf16 g_h_h   [NTOK * D];
__device__ __align__(16) bf16 g_h_l   [NTOK * D];
__device__ __align__(16) bf16 g_mem_h [NTOK * D];
__device__ __align__(16) bf16 g_mem_l [NTOK * D];
__device__ __align__(16) bf16 g_mem2_h[NTOK * D];
__device__ __align__(16) bf16 g_mem2_l[NTOK * D];
__device__ __align__(16) bf16 g_ao_h  [NTOK * D];
__device__ __align__(16) bf16 g_ao_l  [NTOK * D];
__device__ __align__(16) bf16 g_ff_h  [NTOK * 4 * D];
__device__ __align__(16) bf16 g_ff_l  [NTOK * 4 * D];

// weight hi/lo buffers
__device__ __align__(16) bf16 g_wsa_h [6 * 1152 * 384];
__device__ __align__(16) bf16 g_wsa_l [6 * 1152 * 384];
__device__ __align__(16) bf16 g_wsao_h[6 * 384 * 384];
__device__ __align__(16) bf16 g_wsao_l[6 * 384 * 384];
__device__ __align__(16) bf16 g_wca_h [6 * 1152 * 384];
__device__ __align__(16) bf16 g_wca_l [6 * 1152 * 384];
__device__ __align__(16) bf16 g_wcao_h[6 * 384 * 384];
__device__ __align__(16) bf16 g_wcao_l[6 * 384 * 384];
__device__ __align__(16) bf16 g_wf1_h [6 * 1536 * 384];
__device__ __align__(16) bf16 g_wf1_l [6 * 1536 * 384];
__device__ __align__(16) bf16 g_wf2_h [6 * 384 * 1536];
__device__ __align__(16) bf16 g_wf2_l [6 * 384 * 1536];

// ---------------- helpers ----------------
__device__ __forceinline__ uint32_t s2u(const void* p) {
    uint32_t a;
    asm("{ .reg .u64 t; cvta.to.shared.u64 t, %1; cvt.u32.u64 %0, t; }" : "=r"(a) : "l"(p));
    return a;
}
__device__ __forceinline__ void ldm4(uint32_t& r0, uint32_t& r1, uint32_t& r2, uint32_t& r3,
                                     uint32_t a) {
    asm volatile("ldmatrix.sync.aligned.m8n8.x4.shared.b16 {%0,%1,%2,%3}, [%4];"
                 : "=r"(r0), "=r"(r1), "=r"(r2), "=r"(r3) : "r"(a));
}
__device__ __forceinline__ void mma16816(float* d, const uint32_t* a, const uint32_t* b) {
    asm volatile("mma.sync.aligned.m16n8k16.row.col.f32.bf16.bf16.f32 "
                 "{%0,%1,%2,%3}, {%4,%5,%6,%7}, {%8,%9}, {%0,%1,%2,%3};"
                 : "+f"(d[0]), "+f"(d[1]), "+f"(d[2]), "+f"(d[3])
                 : "r"(a[0]), "r"(a[1]), "r"(a[2]), "r"(a[3]), "r"(b[0]), "r"(b[1]));
}
__device__ __forceinline__ void split_store(float v, bf16* hp, bf16* lp) {
    bf16 h = __float2bfloat16(v);
    *hp = h;
    *lp = __float2bfloat16(v - __bfloat162float(h));
}

// ---------------- sim = einsum('bhd,bnd->bhn')  (exact fp32) ----------------
__global__ __launch_bounds__(128) void sim_kernel(const float* __restrict__ qt,
                                                  const float* __restrict__ nd) {
    __shared__ float qs[S * D];
    int b = blockIdx.y;
    int tid = threadIdx.x;
    const float4* qb = (const float4*)(qt + (size_t)b * S * D);
    for (int i = tid; i < S * D / 4; i += 128) ((float4*)qs)[i] = qb[i];
    __syncthreads();

    int r0 = blockIdx.x * 256 + tid;
    int r1 = r0 + 128;
    const float4* n0 = (const float4*)(nd + ((size_t)b * NDN + r0) * D);
    const float4* n1 = (const float4*)(nd + ((size_t)b * NDN + r1) * D);
    const float4* q4 = (const float4*)qs;

    float acc0[S], acc1[S];
#pragma unroll
    for (int h = 0; h < S; h++) { acc0[h] = 0.f; acc1[h] = 0.f; }
    for (int d = 0; d < D / 4; d++) {
        float4 a = n0[d];
        float4 c = n1[d];
#pragma unroll
        for (int h = 0; h < S; h++) {
            float4 q = q4[h * (D / 4) + d];
            acc0[h] += a.x * q.x + a.y * q.y + a.z * q.z + a.w * q.w;
            acc1[h] += c.x * q.x + c.y * q.y + c.z * q.z + c.w * q.w;
        }
    }
#pragma unroll
    for (int h = 0; h < S; h++) {
        g_sim[((size_t)b * S + h) * NDN + r0] = acc0[h];
        g_sim[((size_t)b * S + h) * NDN + r1] = acc1[h];
    }
}

// ---------------- top-k ----------------
__global__ __launch_bounds__(256) void topk_kernel() {
    int row = blockIdx.x;
    __shared__ float vals[NDN];
    __shared__ float sv[256];
    __shared__ int   si[256];
    int tid = threadIdx.x;
    const float4* src = (const float4*)(g_sim + (size_t)row * NDN);
    for (int i = tid; i < NDN / 4; i += 256) ((float4*)vals)[i] = src[i];
    __syncthreads();
    for (int k = 0; k < KN; k++) {
        float bv = -3.4e38f; int bi = 0;
        for (int j = tid; j < NDN; j += 256) {
            float v = vals[j];
            if (v > bv) { bv = v; bi = j; }
        }
        sv[tid] = bv; si[tid] = bi;
        __syncthreads();
        for (int s = 128; s > 0; s >>= 1) {
            if (tid < s) {
                float v2 = sv[tid + s]; int i2 = si[tid + s];
                if (v2 > sv[tid] || (v2 == sv[tid] && i2 < si[tid])) { sv[tid] = v2; si[tid] = i2; }
            }
            __syncthreads();
        }
        if (tid == 0) { g_idx[row * KN + k] = si[0]; vals[si[0]] = -3.4e38f; }
        __syncthreads();
    }
}

// ---------------- build x (fp32) and mem (bf16 hi/lo) ----------------
__global__ __launch_bounds__(96) void init_kernel(const float* __restrict__ qt,
                                                  const float* __restrict__ nd) {
    int tok = blockIdx.x;
    int seq = blockIdx.y;
    int b = seq / KN, kn = seq - b * KN;
    int tid = threadIdx.x;
    const float4* qrow = (const float4*)(qt + ((size_t)b * S + tok) * D);
    int nid = g_idx[(b * S + tok) * KN + kn];
    const float4* nrow = (const float4*)(nd + ((size_t)b * NDN + nid) * D);
    size_t ro = ((size_t)seq * S + tok) * D;
    ((float4*)(g_x + ro))[tid] = qrow[tid];
    float4 m = nrow[tid];
    split_store(m.x, g_mem_h + ro + tid * 4 + 0, g_mem_l + ro + tid * 4 + 0);
    split_store(m.y, g_mem_h + ro + tid * 4 + 1, g_mem_l + ro + tid * 4 + 1);
    split_store(m.z, g_mem_h + ro + tid * 4 + 2, g_mem_l + ro + tid * 4 + 2);
    split_store(m.w, g_mem_h + ro + tid * 4 + 3, g_mem_l + ro + tid * 4 + 3);
}

// ---------------- weight split-convert ----------------
__global__ __launch_bounds__(256) void conv_kernel(const float* __restrict__ src,
                                                   bf16* __restrict__ hi,
                                                   bf16* __restrict__ lo, int n4) {
    int i = blockIdx.x * 256 + threadIdx.x;
    if (i >= n4) return;
    float4 v = ((const float4*)src)[i];
    split_store(v.x, hi + i * 4 + 0, lo + i * 4 + 0);
    split_store(v.y, hi + i * 4 + 1, lo + i * 4 + 1);
    split_store(v.z, hi + i * 4 + 2, lo + i * 4 + 2);
    split_store(v.w, hi + i * 4 + 3, lo + i * 4 + 3);
}

// ---------------- layernorm: MODE 0 = pair, 1 = pair+fp32, 2 = fp32 ----------------
template <int MODE>
__global__ __launch_bounds__(128) void ln_kernel(const float* __restrict__ src,
                                                 const float* __restrict__ w,
                                                 const float* __restrict__ b,
                                                 bf16* __restrict__ dh,
                                                 bf16* __restrict__ dl,
                                                 float* __restrict__ df) {
    int row = blockIdx.x;
    int tid = threadIdx.x;
    const float* x = src + (size_t)row * D;
    float v0 = x[tid], v1 = x[tid + 128], v2 = x[tid + 256];
    float s  = v0 + v1 + v2;
    float s2 = v0 * v0 + v1 * v1 + v2 * v2;
    for (int o = 16; o > 0; o >>= 1) {
        s  += __shfl_xor_sync(0xffffffffu, s,  o);
        s2 += __shfl_xor_sync(0xffffffffu, s2, o);
    }
    __shared__ float ss[4], ss2[4];
    if ((tid & 31) == 0) { ss[tid >> 5] = s; ss2[tid >> 5] = s2; }
    __syncthreads();
    s  = ss[0]  + ss[1]  + ss[2]  + ss[3];
    s2 = ss2[0] + ss2[1] + ss2[2] + ss2[3];
    float mu  = s * (1.f / D);
    float var = s2 * (1.f / D) - mu * mu;
    float rs  = rsqrtf(var + 1e-5f);
    float o0 = (v0 - mu) * rs * w[tid]       + b[tid];
    float o1 = (v1 - mu) * rs * w[tid + 128] + b[tid + 128];
    float o2 = (v2 - mu) * rs * w[tid + 256] + b[tid + 256];
    size_t ro = (size_t)row * D;
    if (MODE <= 1) {
        split_store(o0, dh + ro + tid,       dl + ro + tid);
        split_store(o1, dh + ro + tid + 128, dl + ro + tid + 128);
        split_store(o2, dh + ro + tid + 256, dl + ro + tid + 256);
    }
    if (MODE >= 1) {
        df[ro + tid]       = o0;
        df[ro + tid + 128] = o1;
        df[ro + tid + 256] = o2;
    }
}

// ---------------- mma.sync GEMM: C[M,N] = A[M,K] @ W[N,K]^T + bias (+epi) ----------------
// bf16x3 split products, fp32 accum. BM=128, BN=64, BK=64, 8 warps (4x2), warp tile 32x32.
// EPI: 0 = fp32 C, 1 = exact gelu -> bf16 pair (Chi/Clo), 2 = + residual -> fp32 C
#define SM_AH 0
#define SM_AL 16384
#define SM_WH 32768
#define SM_WL 40960

template <int EPI>
__global__ __launch_bounds__(256, 2) void gemm_mma(const bf16* __restrict__ Ah,
                                                   const bf16* __restrict__ Al, int lda,
                                                   const bf16* __restrict__ Wh,
                                                   const bf16* __restrict__ Wl, int ldw,
                                                   const float* __restrict__ bias,
                                                   float* __restrict__ C,
                                                   bf16* __restrict__ Chi, bf16* __restrict__ Clo,
                                                   int ldc,
                                                   const float* __restrict__ res, int K) {
    __shared__ __align__(128) char smem[49152];
    uint32_t sb = s2u(smem);
    int tid = threadIdx.x, wid = tid >> 5, lane = tid & 31;
    int m0 = blockIdx.x * 128, n0 = blockIdx.y * 64;
    int wm = wid & 3, wn = wid >> 2;

    float acc[2][4][4];
#pragma unroll
    for (int i = 0; i < 2; i++)
#pragma unroll
        for (int j = 0; j < 4; j++)
#pragma unroll
            for (int k = 0; k < 4; k++) acc[i][j][k] = 0.f;

    // ldmatrix lane-address components (same formula for A and B tiles)
    int fr  = ((lane >> 3) & 1) * 8 + (lane & 7);   // row within 16-row tile
    int fkc = lane >> 4;                            // 16B k-chunk within k16 step

    for (int kt = 0; kt < K; kt += 64) {
        // ---- load A (128x64) hi/lo ----
#pragma unroll
        for (int u = 0; u < 4; u++) {
            int idx = tid + u * 256;                // 1024 16B-chunks
            int row = idx >> 3, c = idx & 7;
            uint32_t so = (uint32_t)(row * 128 + c * 16);
            so ^= (so >> 3) & 0x70;
            size_t ga = (size_t)(m0 + row) * lda + kt + c * 8;
            *(uint4*)(smem + SM_AH + so) = *(const uint4*)(Ah + ga);
            *(uint4*)(smem + SM_AL + so) = *(const uint4*)(Al + ga);
        }
        // ---- load W (64x64) hi/lo ----
#pragma unroll
        for (int u = 0; u < 2; u++) {
            int idx = tid + u * 256;                // 512 chunks
            int row = idx >> 3, c = idx & 7;
            uint32_t so = (uint32_t)(row * 128 + c * 16);
            so ^= (so >> 3) & 0x70;
            size_t gw = (size_t)(n0 + row) * ldw + kt + c * 8;
            *(uint4*)(smem + SM_WH + so) = *(const uint4*)(Wh + gw);
            *(uint4*)(smem + SM_WL + so) = *(const uint4*)(Wl + gw);
        }
        __syncthreads();

#pragma unroll
        for (int ks = 0; ks < 4; ks++) {
            uint32_t aH[2][4], aL[2][4], bH[4][2], bL[4][2];
            int kc = ks * 2 + fkc;
            // A fragments: 2 m-tiles of 16 rows
#pragma unroll
            for (int mt = 0; mt < 2; mt++) {
                int row = wm * 32 + mt * 16 + fr;
                uint32_t off = (uint32_t)(row * 128 + kc * 16);
                off ^= (off >> 3) & 0x70;
                ldm4(aH[mt][0], aH[mt][1], aH[mt][2], aH[mt][3], sb + SM_AH + off);
                ldm4(aL[mt][0], aL[mt][1], aL[mt][2], aL[mt][3], sb + SM_AL + off);
            }
            // B fragments: 2 pairs of n-tiles (each pair = 16 n-rows -> 2 tiles)
#pragma unroll
            for (int p = 0; p < 2; p++) {
                int row = wn * 32 + p * 16 + fr;
                uint32_t off = (uint32_t)(row * 128 + kc * 16);
                off ^= (off >> 3) & 0x70;
                uint32_t t0, t1, t2, t3;
                ldm4(t0, t1, t2, t3, sb + SM_WH + off);
                bH[p * 2][0] = t0; bH[p * 2 + 1][0] = t1;
                bH[p * 2][1] = t2; bH[p * 2 + 1][1] = t3;
                ldm4(t0, t1, t2, t3, sb + SM_WL + off);
                bL[p * 2][0] = t0; bL[p * 2 + 1][0] = t1;
                bL[p * 2][1] = t2; bL[p * 2 + 1][1] = t3;
            }
#pragma unroll
            for (int mt = 0; mt < 2; mt++)
#pragma unroll
                for (int nt = 0; nt < 4; nt++) {
                    mma16816(acc[mt][nt], aH[mt], bH[nt]);
                    mma16816(acc[mt][nt], aH[mt], bL[nt]);
                    mma16816(acc[mt][nt], aL[mt], bH[nt]);
                }
        }
        __syncthreads();
    }

    // ---- epilogue ----
    int g = lane >> 2, tg = lane & 3;
#pragma unroll
    for (int mt = 0; mt < 2; mt++)
#pragma unroll
        for (int nt = 0; nt < 4; nt++) {
            int n = n0 + wn * 32 + nt * 8 + tg * 2;
            int ma = m0 + wm * 32 + mt * 16 + g;
            int mb = ma + 8;
            float b0 = bias[n], b1 = bias[n + 1];
            float v00 = acc[mt][nt][0] + b0;
            float v01 = acc[mt][nt][1] + b1;
            float v10 = acc[mt][nt][2] + b0;
            float v11 = acc[mt][nt][3] + b1;
            if (EPI == 1) {
                v00 = 0.5f * v00 * (1.f + erff(v00 * 0.70710678118654752f));
                v01 = 0.5f * v01 * (1.f + erff(v01 * 0.70710678118654752f));
                v10 = 0.5f * v10 * (1.f + erff(v10 * 0.70710678118654752f));
                v11 = 0.5f * v11 * (1.f + erff(v11 * 0.70710678118654752f));
                split_store(v00, Chi + (size_t)ma * ldc + n,     Clo + (size_t)ma * ldc + n);
                split_store(v01, Chi + (size_t)ma * ldc + n + 1, Clo + (size_t)ma * ldc + n + 1);
                split_store(v10, Chi + (size_t)mb * ldc + n,     Clo + (size_t)mb * ldc + n);
                split_store(v11, Chi + (size_t)mb * ldc + n + 1, Clo + (size_t)mb * ldc + n + 1);
            } else {
                if (EPI == 2) {
                    v00 += res[(size_t)ma * D + n];
                    v01 += res[(size_t)ma * D + n + 1];
                    v10 += res[(size_t)mb * D + n];
                    v11 += res[(size_t)mb * D + n + 1];
                }
                *(float2*)(C + (size_t)ma * ldc + n) = make_float2(v00, v01);
                *(float2*)(C + (size_t)mb * ldc + n) = make_float2(v10, v11);
            }
        }
}

// ---------------- attention (one block per (head, seq)) ----------------
__global__ __launch_bounds__(256) void attn_kernel() {
    int head = blockIdx.x;
    int seq  = blockIdx.y;
    __shared__ float q[S * HD], k[S * HD], v[S * HD];
    __shared__ float sc[S][S + 2];
    int tid = threadIdx.x;
    size_t base = (size_t)seq * S * (3 * D) + head * HD;
    for (int idx = tid; idx < S * HD; idx += 256) {
        int i = idx / HD, e = idx - i * HD;
        size_t g = base + (size_t)i * (3 * D) + e;
        q[idx] = g_qkv[g];
        k[idx] = g_qkv[g + D];
        v[idx] = g_qkv[g + 2 * D];
    }
    __syncthreads();
    if (tid < S * S) {
        int i = tid / S, j = tid - i * S;
        float s = 0.f;
#pragma unroll
        for (int e = 0; e < HD; e++) s += q[i * HD + e] * k[j * HD + e];
        sc[i][j] = s * 0.14433756729740643f;
    }
    __syncthreads();
    if (tid < S) {
        float mx = -3.4e38f;
        for (int j = 0; j < S; j++) mx = fmaxf(mx, sc[tid][j]);
        float e[S];
        float sum = 0.f;
        for (int j = 0; j < S; j++) { e[j] = expf(sc[tid][j] - mx); sum += e[j]; }
        float inv = 1.f / sum;
        for (int j = 0; j < S; j++) sc[tid][j] = e[j] * inv;
    }
    __syncthreads();
    for (int idx = tid; idx < S * HD; idx += 256) {
        int i = idx / HD, e = idx - i * HD;
        float o = 0.f;
#pragma unroll
        for (int j = 0; j < S; j++) o += sc[i][j] * v[j * HD + e];
        size_t go = ((size_t)seq * S + i) * D + head * HD + e;
        split_store(o, g_ao_h + go, g_ao_l + go);
    }
}

// ---------------- launch ----------------
extern "C" void kernel_launch(void* const* d_in, const int* in_sizes, int n_in,
                              void* d_out, int out_size) {
    const float* qt    = (const float*)d_in[0];
    const float* nd    = (const float*)d_in[1];
    const float* sa_w  = (const float*)d_in[2];
    const float* sa_b  = (const float*)d_in[3];
    const float* sa_ow = (const float*)d_in[4];
    const float* sa_ob = (const float*)d_in[5];
    const float* ca_w  = (const float*)d_in[6];
    const float* ca_b  = (const float*)d_in[7];
    const float* ca_ow = (const float*)d_in[8];
    const float* ca_ob = (const float*)d_in[9];
    const float* ln1w  = (const float*)d_in[10];
    const float* ln1b  = (const float*)d_in[11];
    const float* ln2w  = (const float*)d_in[12];
    const float* ln2b  = (const float*)d_in[13];
    const float* ln3w  = (const float*)d_in[14];
    const float* ln3b  = (const float*)d_in[15];
    const float* f1w   = (const float*)d_in[16];
    const float* f1b   = (const float*)d_in[17];
    const float* f2w   = (const float*)d_in[18];
    const float* f2b   = (const float*)d_in[19];
    const float* fnw   = (const float*)d_in[20];
    const float* fnb   = (const float*)d_in[21];
    float* out = (float*)d_out;

    float *p_x, *p_qkv;
    bf16 *hh, *hl, *memh, *meml, *mem2h, *mem2l, *aoh, *aol, *ffh, *ffl;
    bf16 *wsah, *wsal, *wsaoh, *wsaol, *wcah, *wcal, *wcaoh, *wcaol, *wf1h, *wf1l, *wf2h, *wf2l;
    cudaGetSymbolAddress((void**)&p_x,   g_x);
    cudaGetSymbolAddress((void**)&p_qkv, g_qkv);
    cudaGetSymbolAddress((void**)&hh,    g_h_h);
    cudaGetSymbolAddress((void**)&hl,    g_h_l);
    cudaGetSymbolAddress((void**)&memh,  g_mem_h);
    cudaGetSymbolAddress((void**)&meml,  g_mem_l);
    cudaGetSymbolAddress((void**)&mem2h, g_mem2_h);
    cudaGetSymbolAddress((void**)&mem2l, g_mem2_l);
    cudaGetSymbolAddress((void**)&aoh,   g_ao_h);
    cudaGetSymbolAddress((void**)&aol,   g_ao_l);
    cudaGetSymbolAddress((void**)&ffh,   g_ff_h);
    cudaGetSymbolAddress((void**)&ffl,   g_ff_l);
    cudaGetSymbolAddress((void**)&wsah,  g_wsa_h);
    cudaGetSymbolAddress((void**)&wsal,  g_wsa_l);
    cudaGetSymbolAddress((void**)&wsaoh, g_wsao_h);
    cudaGetSymbolAddress((void**)&wsaol, g_wsao_l);
    cudaGetSymbolAddress((void**)&wcah,  g_wca_h);
    cudaGetSymbolAddress((void**)&wcal,  g_wca_l);
    cudaGetSymbolAddress((void**)&wcaoh, g_wcao_h);
    cudaGetSymbolAddress((void**)&wcaol, g_wcao_l);
    cudaGetSymbolAddress((void**)&wf1h,  g_wf1_h);
    cudaGetSymbolAddress((void**)&wf1l,  g_wf1_l);
    cudaGetSymbolAddress((void**)&wf2h,  g_wf2_h);
    cudaGetSymbolAddress((void**)&wf2l,  g_wf2_l);

    // weight split-conversion (every call; deterministic)
    {
        int n;
        n = 6 * 1152 * 384 / 4; conv_kernel<<<(n + 255) / 256, 256>>>(sa_w,  wsah,  wsal,  n);
        n = 6 * 384 * 384 / 4;  conv_kernel<<<(n + 255) / 256, 256>>>(sa_ow, wsaoh, wsaol, n);
        n = 6 * 1152 * 384 / 4; conv_kernel<<<(n + 255) / 256, 256>>>(ca_w,  wcah,  wcal,  n);
        n = 6 * 384 * 384 / 4;  conv_kernel<<<(n + 255) / 256, 256>>>(ca_ow, wcaoh, wcaol, n);
        n = 6 * 1536 * 384 / 4; conv_kernel<<<(n + 255) / 256, 256>>>(f1w,   wf1h,  wf1l,  n);
        n = 6 * 384 * 1536 / 4; conv_kernel<<<(n + 255) / 256, 256>>>(f2w,   wf2h,  wf2l,  n);
    }

    sim_kernel<<<dim3(NDN / 256, NB), 128>>>(qt, nd);
    topk_kernel<<<NB * S, 256>>>();
    init_kernel<<<dim3(S, NSEQ), 96>>>(qt, nd);

    const int GM = NTOK / 128;   // 70
    for (int i = 0; i < 6; i++) {
        const bf16* mh = (i < 3) ? memh : mem2h;
        const bf16* ml = (i < 3) ? meml : mem2l;
        // --- self attention ---
        ln_kernel<0><<<NTOK, 128>>>(p_x, ln1w + i * D, ln1b + i * D, hh, hl, nullptr);
        gemm_mma<0><<<dim3(GM, 18), 256>>>(hh, hl, D,
            wsah + (size_t)i * 1152 * 384, wsal + (size_t)i * 1152 * 384, D,
            sa_b + i * 1152, p_qkv, nullptr, nullptr, 3 * D, nullptr, D);
        attn_kernel<<<dim3(NH, NSEQ), 256>>>();
        gemm_mma<2><<<dim3(GM, 6), 256>>>(aoh, aol, D,
            wsaoh + (size_t)i * 384 * 384, wsaol + (size_t)i * 384 * 384, D,
            sa_ob + i * D, p_x, nullptr, nullptr, D, p_x, D);
        // --- cross attention ---
        ln_kernel<0><<<NTOK, 128>>>(p_x, ln2w + i * D, ln2b + i * D, hh, hl, nullptr);
        gemm_mma<0><<<dim3(GM, 6), 256>>>(hh, hl, D,
            wcah + (size_t)i * 1152 * 384, wcal + (size_t)i * 1152 * 384, D,
            ca_b + i * 1152, p_qkv, nullptr, nullptr, 3 * D, nullptr, D);
        gemm_mma<0><<<dim3(GM, 12), 256>>>(mh, ml, D,
            wcah + (size_t)i * 1152 * 384 + (size_t)384 * 384,
            wcal + (size_t)i * 1152 * 384 + (size_t)384 * 384, D,
            ca_b + i * 1152 + D, p_qkv + D, nullptr, nullptr, 3 * D, nullptr, D);
        attn_kernel<<<dim3(NH, NSEQ), 256>>>();
        gemm_mma<2><<<dim3(GM, 6), 256>>>(aoh, aol, D,
            wcaoh + (size_t)i * 384 * 384, wcaol + (size_t)i * 384 * 384, D,
            ca_ob + i * D, p_x, nullptr, nullptr, D, p_x, D);
        // --- FFN ---
        ln_kernel<0><<<NTOK, 128>>>(p_x, ln3w + i * D, ln3b + i * D, hh, hl, nullptr);
        gemm_mma<1><<<dim3(GM, 24), 256>>>(hh, hl, D,
            wf1h + (size_t)i * 1536 * 384, wf1l + (size_t)i * 1536 * 384, D,
            f1b + i * 1536, nullptr, ffh, ffl, 1536, nullptr, D);
        gemm_mma<2><<<dim3(GM, 6), 256>>>(ffh, ffl, 1536,
            wf2h + (size_t)i * 384 * 1536, wf2l + (size_t)i * 384 * 1536, 1536,
            f2b + i * D, p_x, nullptr, nullptr, D, p_x, 1536);
        // --- mid final-norm: x = ln(x) in place; mem2 = split(x) ---
        if (i == 2)
            ln_kernel<1><<<NTOK, 128>>>(p_x, fnw, fnb, mem2h, mem2l, p_x);
    }
    ln_kernel<2><<<NTOK, 128>>>(p_x, fnw + D, fnb + D, nullptr, nullptr, out);
}